// round 11
// baseline (speedup 1.0000x reference)
#include <cuda_runtime.h>
#include <cuda_bf16.h>
#include <cstdint>

#define NN      50000
#define EE      800000
#define DINV    256
#define HD      128
#define RRk     8
#define NHEADS  8
#define DHH     16
#define P24     24            // B smem pitch in bf16 (48B): conflict-free ldmatrix
#define NBINS   (NN * RRk)

// rgcn_all9 smem layout: A resident (XOR 32B-pitch, no padding) + B 2-stage P24
#define ACHX    4096                      // bytes per A chunk (128 rows x 32B)
#define A_ARR   (8 * ACHX)                // 32KB per A array (hi or lo)
#define BSTG    (128 * P24 * 2)           // 6144 bytes per B stage array
#define RGCN9_SMEM (2 * A_ARR + 4 * BSTG) // 90112 bytes -> 2 CTAs/SM

// ---------------- scratch (static device arrays; no cudaMalloc) -------------
__device__ float g_h1[(size_t)NN * HD];
__device__ float g_h2[(size_t)NN * HD];
__device__ float g_num[(size_t)NN * HD];
__device__ int   g_deg[(size_t)NN * RRk];
__device__ float g_asrc[(size_t)NN * NHEADS];
__device__ float g_atgt[(size_t)NN * NHEADS];
__device__ float g_denom[(size_t)NN * NHEADS];

// CSR by (src, rel): bins of one src are contiguous
__device__ int  g_cnt[NBINS];
__device__ int  g_ptr[NBINS];
__device__ int  g_off[NBINS];
__device__ int  g_bsum[512];
__device__ int2 g_eTI[EE];        // (tgt, bitcast inv_deg)

__device__ __nv_bfloat16 g_xhi[(size_t)NN * DINV];
__device__ __nv_bfloat16 g_xlo[(size_t)NN * DINV];
__device__ __nv_bfloat16 g_fhi[(size_t)NN * HD];
__device__ __nv_bfloat16 g_flo[(size_t)NN * HD];
// dedicated weight buffers (enable overlap of all prep kernels)
__device__ __nv_bfloat16 g_wph[DINV * HD], g_wpl[DINV * HD];
__device__ __nv_bfloat16 g_w1h[(RRk + 1) * HD * HD], g_w1l[(RRk + 1) * HD * HD];
__device__ __nv_bfloat16 g_w2h[(RRk + 1) * HD * HD], g_w2l[(RRk + 1) * HD * HD];
__device__ __nv_bfloat16 g_wgh[HD * HD], g_wgl[HD * HD];

// ---------------- PTX helpers -------------------------------------------------
__device__ __forceinline__ uint32_t smem_to_u32(const void* p) {
    uint32_t a;
    asm("{ .reg .u64 t; cvta.to.shared.u64 t, %1; cvt.u32.u64 %0, t; }" : "=r"(a) : "l"(p));
    return a;
}
__device__ __forceinline__ void ldm_x4(unsigned* r, uint32_t a) {
    asm volatile("ldmatrix.sync.aligned.m8n8.x4.shared.b16 {%0,%1,%2,%3}, [%4];"
                 : "=r"(r[0]), "=r"(r[1]), "=r"(r[2]), "=r"(r[3]) : "r"(a));
}
__device__ __forceinline__ void mma_bf16(float* d, const unsigned* a, const unsigned* b) {
    asm volatile("mma.sync.aligned.m16n8k16.row.col.f32.bf16.bf16.f32 "
                 "{%0,%1,%2,%3}, {%4,%5,%6,%7}, {%8,%9}, {%0,%1,%2,%3};"
                 : "+f"(d[0]), "+f"(d[1]), "+f"(d[2]), "+f"(d[3])
                 : "r"(a[0]), "r"(a[1]), "r"(a[2]), "r"(a[3]), "r"(b[0]), "r"(b[1]));
}
__device__ __forceinline__ void cpa16(uint32_t dst, const void* src, int szbytes) {
    asm volatile("cp.async.ca.shared.global [%0], [%1], 16, %2;"
                 :: "r"(dst), "l"(src), "r"(szbytes) : "memory");
}
#define CP_COMMIT()  asm volatile("cp.async.commit_group;" ::: "memory")
#define CP_WAIT(n)   asm volatile("cp.async.wait_group %0;" :: "n"(n) : "memory")

__device__ __forceinline__ void red_add_v4(float* p, float a, float b, float c, float d) {
    asm volatile("red.global.add.v4.f32 [%0], {%1, %2, %3, %4};"
                 :: "l"(p), "f"(a), "f"(b), "f"(c), "f"(d) : "memory");
}
__device__ __forceinline__ void red_add_v2(float* p, float a, float b) {
    asm volatile("red.global.add.v2.f32 [%0], {%1, %2};"
                 :: "l"(p), "f"(a), "f"(b) : "memory");
}

// ---------------- generic GEMM (2-stage cp.async, used for proj / GAT z) ------
#define STG (128 * P24)

__global__ __launch_bounds__(256)
void gemm_mma(const __nv_bfloat16* __restrict__ Ahi, const __nv_bfloat16* __restrict__ Alo,
              int Ktot,
              const __nv_bfloat16* __restrict__ Bhi, const __nv_bfloat16* __restrict__ Blo,
              const float* __restrict__ bias,
              float* __restrict__ C, int M)
{
    __shared__ __align__(16) uint16_t sAh[2 * STG], sAl[2 * STG];
    __shared__ __align__(16) uint16_t sBh[2 * STG], sBl[2 * STG];

    const int tid    = threadIdx.x;
    const int lane   = tid & 31, wid = tid >> 5;
    const int warp_m = wid & 1;
    const int warp_n = wid >> 1;
    const int m0     = blockIdx.x * 128;
    const int lrow  = tid >> 1, lhalf = tid & 1;
    const int jj    = lane >> 3, rin = lane & 7;
    const int a_r   = (jj & 1) * 8 + rin;
    const int a_c   = (jj >> 1) * 8;
    const uint32_t bAh = smem_to_u32(sAh), bAl = smem_to_u32(sAl);
    const uint32_t bBh = smem_to_u32(sBh), bBl = smem_to_u32(sBl);
    const uint32_t soff = (lrow * P24 + lhalf * 8) * 2;
    const int gr = m0 + lrow;
    const int aSz = (gr < M) ? 16 : 0;
    const size_t aRow = (size_t)((gr < M) ? gr : 0) * Ktot + lhalf * 8;
    const size_t bRow = (size_t)lrow * Ktot + lhalf * 8;

    float acc[4][4][4];
#pragma unroll
    for (int i = 0; i < 4; i++)
#pragma unroll
        for (int j = 0; j < 4; j++)
#pragma unroll
            for (int q = 0; q < 4; q++) acc[i][j][q] = 0.f;

    const int nIter = Ktot >> 4;
    cpa16(bAh + soff, Ahi + aRow, aSz);
    cpa16(bAl + soff, Alo + aRow, aSz);
    cpa16(bBh + soff, Bhi + bRow, 16);
    cpa16(bBl + soff, Blo + bRow, 16);
    CP_COMMIT();

    for (int it = 0; it < nIter; it++) {
        if (it + 1 < nIter) {
            uint32_t st = ((it + 1) & 1) * STG * 2;
            int k0 = (it + 1) << 4;
            cpa16(bAh + st + soff, Ahi + aRow + k0, aSz);
            cpa16(bAl + st + soff, Alo + aRow + k0, aSz);
            cpa16(bBh + st + soff, Bhi + bRow + k0, 16);
            cpa16(bBl + st + soff, Blo + bRow + k0, 16);
            CP_COMMIT(); CP_WAIT(1);
        } else { CP_WAIT(0); }
        __syncthreads();

        const uint32_t st = (it & 1) * STG * 2;
        unsigned ah[4][4], al[4][4], bh[4][2], bl[4][2];
#pragma unroll
        for (int i = 0; i < 4; i++) {
            int row = warp_m * 64 + i * 16 + a_r;
            ldm_x4(ah[i], bAh + st + (row * P24 + a_c) * 2);
            ldm_x4(al[i], bAl + st + (row * P24 + a_c) * 2);
        }
#pragma unroll
        for (int p = 0; p < 2; p++) {
            int row = warp_n * 32 + p * 16 + a_r;
            unsigned t[4];
            ldm_x4(t, bBh + st + (row * P24 + a_c) * 2);
            bh[p * 2][0] = t[0]; bh[p * 2][1] = t[2];
            bh[p * 2 + 1][0] = t[1]; bh[p * 2 + 1][1] = t[3];
            ldm_x4(t, bBl + st + (row * P24 + a_c) * 2);
            bl[p * 2][0] = t[0]; bl[p * 2][1] = t[2];
            bl[p * 2 + 1][0] = t[1]; bl[p * 2 + 1][1] = t[3];
        }
#pragma unroll
        for (int i = 0; i < 4; i++)
#pragma unroll
            for (int j = 0; j < 4; j++) {
                mma_bf16(acc[i][j], ah[i], bh[j]);
                mma_bf16(acc[i][j], ah[i], bl[j]);
                mma_bf16(acc[i][j], al[i], bh[j]);
            }
        __syncthreads();
    }

    const int mrow = m0 + warp_m * 64 + (lane >> 2);
    const int ncol = warp_n * 32 + (lane & 3) * 2;
#pragma unroll
    for (int i = 0; i < 4; i++) {
#pragma unroll
        for (int j = 0; j < 4; j++) {
            int col = ncol + j * 8;
            float bv0 = bias ? bias[col] : 0.f;
            float bv1 = bias ? bias[col + 1] : 0.f;
            int mm = mrow + i * 16;
            if (mm < M)
                *reinterpret_cast<float2*>(C + (size_t)mm * HD + col) =
                    make_float2(acc[i][j][0] + bv0, acc[i][j][1] + bv1);
            if (mm + 8 < M)
                *reinterpret_cast<float2*>(C + (size_t)(mm + 8) * HD + col) =
                    make_float2(acc[i][j][2] + bv0, acc[i][j][3] + bv1);
        }
    }
}

// ---------------- A-resident full RGCN layer ----------------------------------
// One CTA per 128-row m-block. A (hi/lo) resident in smem for all 9 slabs
// (slab 0 = root, 1..8 = relations); B double-buffered per 16-k chunk.
// Per-slab epilogue: root adds into zeroed H; relations scatter via CSR bins.
// A layout: 8 chunks of 128 rows x 32B; 16B unit (row, q) at
//   chunk*4096 + row*32 + ((q ^ ((row>>2)&1)) << 4)      (conflict-free ldmatrix)
__global__ __launch_bounds__(256, 2)
void rgcn_all9(const __nv_bfloat16* __restrict__ Ahi, const __nv_bfloat16* __restrict__ Alo,
               const __nv_bfloat16* __restrict__ BhiAll, const __nv_bfloat16* __restrict__ BloAll,
               float* __restrict__ H, int M)
{
    extern __shared__ __align__(16) char dsm[];
    const uint32_t bAh = smem_to_u32(dsm);
    const uint32_t bAl = bAh + A_ARR;
    const uint32_t bBh = bAh + 2 * A_ARR;
    const uint32_t bBl = bBh + 2 * BSTG;

    const int tid    = threadIdx.x;
    const int lane   = tid & 31, wid = tid >> 5;
    const int warp_m = wid & 1;
    const int warp_n = wid >> 1;
    const int m0     = blockIdx.x * 128;
    const int lrow  = tid >> 1, lhalf = tid & 1;
    const int jj    = lane >> 3, rin = lane & 7;
    const int a_r   = (jj & 1) * 8 + rin;
    const int a_c   = (jj >> 1) * 8;
    const int a_q   = a_c >> 3;

    const uint32_t bsoff = (lrow * P24 + lhalf * 8) * 2;
    const size_t bRowBase = (size_t)lrow * HD + lhalf * 8;

    // ---- prologue: load full resident A (hi+lo) + B(slab0, chunk0) ----
    {
        const int gr = m0 + lrow;
        const int sz = (gr < M) ? 16 : 0;
        const uint32_t so = lrow * 32 + (((lhalf) ^ ((lrow >> 2) & 1)) << 4);
        const size_t ga = (size_t)((gr < M) ? gr : 0) * HD + lhalf * 8;
#pragma unroll
        for (int c = 0; c < 8; c++) {
            cpa16(bAh + c * ACHX + so, Ahi + ga + c * 16, sz);
            cpa16(bAl + c * ACHX + so, Alo + ga + c * 16, sz);
        }
        cpa16(bBh + bsoff, BhiAll + bRowBase, 16);
        cpa16(bBl + bsoff, BloAll + bRowBase, 16);
        CP_COMMIT();
    }

    float acc[4][4][4];
#pragma unroll
    for (int i = 0; i < 4; i++)
#pragma unroll
        for (int j = 0; j < 4; j++)
#pragma unroll
            for (int q = 0; q < 4; q++) acc[i][j][q] = 0.f;

    const int mBase = m0 + warp_m * 64 + (lane >> 2);
    const int cBase = warp_n * 32 + (lane & 3) * 2;

    for (int idx = 0; idx < 72; idx++) {
        const int s = idx >> 3, k = idx & 7;
        if (idx + 1 < 72) {
            const int s2 = (idx + 1) >> 3, k2 = (idx + 1) & 7;
            const uint32_t st2 = ((idx + 1) & 1) * BSTG;
            const size_t bOff = (size_t)(s2 * 128) * HD + bRowBase + k2 * 16;
            cpa16(bBh + st2 + bsoff, BhiAll + bOff, 16);
            cpa16(bBl + st2 + bsoff, BloAll + bOff, 16);
            CP_COMMIT(); CP_WAIT(1);
        } else { CP_WAIT(0); }
        __syncthreads();

        const uint32_t stB = (idx & 1) * BSTG;
        unsigned ah[4][4], al[4][4], bh[4][2], bl[4][2];
#pragma unroll
        for (int i = 0; i < 4; i++) {
            int row = warp_m * 64 + i * 16 + a_r;
            uint32_t ao = k * ACHX + row * 32 + (((a_q) ^ ((row >> 2) & 1)) << 4);
            ldm_x4(ah[i], bAh + ao);
            ldm_x4(al[i], bAl + ao);
        }
#pragma unroll
        for (int p = 0; p < 2; p++) {
            int row = warp_n * 32 + p * 16 + a_r;
            unsigned t[4];
            ldm_x4(t, bBh + stB + (row * P24 + a_c) * 2);
            bh[p * 2][0] = t[0]; bh[p * 2][1] = t[2];
            bh[p * 2 + 1][0] = t[1]; bh[p * 2 + 1][1] = t[3];
            ldm_x4(t, bBl + stB + (row * P24 + a_c) * 2);
            bl[p * 2][0] = t[0]; bl[p * 2][1] = t[2];
            bl[p * 2 + 1][0] = t[1]; bl[p * 2 + 1][1] = t[3];
        }
#pragma unroll
        for (int i = 0; i < 4; i++)
#pragma unroll
            for (int j = 0; j < 4; j++) {
                mma_bf16(acc[i][j], ah[i], bh[j]);
                mma_bf16(acc[i][j], ah[i], bl[j]);
                mma_bf16(acc[i][j], al[i], bh[j]);
            }
        __syncthreads();

        if (k == 7) {
            if (s == 0) {
                // root: H pre-zeroed, plain atomic add
#pragma unroll
                for (int i = 0; i < 4; i++) {
#pragma unroll
                    for (int p = 0; p < 2; p++) {
                        int m = mBase + i * 16 + p * 8;
                        if (m >= M) continue;
                        float* base = H + (size_t)m * HD + cBase;
#pragma unroll
                        for (int j = 0; j < 4; j++)
                            red_add_v2(base + j * 8, acc[i][j][p * 2], acc[i][j][p * 2 + 1]);
                    }
                }
            } else {
                const int rel = s - 1;
#pragma unroll
                for (int i = 0; i < 4; i++) {
#pragma unroll
                    for (int p = 0; p < 2; p++) {
                        int m = mBase + i * 16 + p * 8;
                        if (m >= M) continue;
                        int bin = (m << 3) + rel;
                        int e0 = bin ? g_ptr[bin - 1] : 0;
                        int e1 = g_ptr[bin];
                        for (int e = e0; e < e1; e++) {
                            int2 ti = g_eTI[e];
                            float inv = __int_as_float(ti.y);
                            float* base = H + (size_t)ti.x * HD + cBase;
#pragma unroll
                            for (int j = 0; j < 4; j++)
                                red_add_v2(base + j * 8,
                                           acc[i][j][p * 2] * inv, acc[i][j][p * 2 + 1] * inv);
                        }
                    }
                }
            }
#pragma unroll
            for (int i = 0; i < 4; i++)
#pragma unroll
                for (int j = 0; j < 4; j++)
#pragma unroll
                    for (int q = 0; q < 4; q++) acc[i][j][q] = 0.f;
        }
    }
}

// ---------------- CSR build ----------------------------------------------------
__global__ void count_kernel(const int* __restrict__ src, const int* __restrict__ tgt,
                             const int* __restrict__ et, int E) {
    int i = blockIdx.x * blockDim.x + threadIdx.x;
    if (i >= E) return;
    int r = et[i];
    atomicAdd(&g_deg[(size_t)tgt[i] * RRk + r], 1);
    atomicAdd(&g_cnt[(size_t)src[i] * RRk + r], 1);
}

__global__ void scan1(int n) {
    __shared__ int sh[1024];
    int i = blockIdx.x * 1024 + threadIdx.x;
    int v = (i < n) ? g_cnt[i] : 0;
    sh[threadIdx.x] = v;
    __syncthreads();
    for (int o = 1; o < 1024; o <<= 1) {
        int t = (threadIdx.x >= o) ? sh[threadIdx.x - o] : 0;
        __syncthreads();
        sh[threadIdx.x] += t;
        __syncthreads();
    }
    if (i < n) g_ptr[i] = sh[threadIdx.x];
    if (threadIdx.x == 1023) g_bsum[blockIdx.x] = sh[1023];
}
__global__ void scan2(int nb) {
    __shared__ int sh[512];
    int v = (threadIdx.x < nb) ? g_bsum[threadIdx.x] : 0;
    sh[threadIdx.x] = v;
    __syncthreads();
    for (int o = 1; o < 512; o <<= 1) {
        int t = (threadIdx.x >= o) ? sh[threadIdx.x - o] : 0;
        __syncthreads();
        sh[threadIdx.x] += t;
        __syncthreads();
    }
    if (threadIdx.x < nb) g_bsum[threadIdx.x] = sh[threadIdx.x];
}
__global__ void scan3(int n) {
    int i = blockIdx.x * 1024 + threadIdx.x;
    if (i >= n || blockIdx.x == 0) return;
    g_ptr[i] += g_bsum[blockIdx.x - 1];
}
__global__ void place_kernel(const int* __restrict__ src, const int* __restrict__ tgt,
                             const int* __restrict__ et, int E) {
    int i = blockIdx.x * blockDim.x + threadIdx.x;
    if (i >= E) return;
    int r = et[i], s = src[i], t = tgt[i];
    int bin = s * RRk + r;
    int base = bin ? g_ptr[bin - 1] : 0;
    int pos = base + atomicAdd(&g_off[bin], 1);
    int d = g_deg[(size_t)t * RRk + r];
    float inv = 1.f / (float)(d > 1 ? d : 1);
    g_eTI[pos] = make_int2(t, __float_as_int(inv));
}

// ---------------- split / weight-prep kernels --------------------------------
__global__ void split_kernel(const float* __restrict__ in, __nv_bfloat16* __restrict__ hi,
                             __nv_bfloat16* __restrict__ lo, int n4,
                             const float* __restrict__ bias, int do_relu) {
    int i = blockIdx.x * blockDim.x + threadIdx.x;
    if (i >= n4) return;
    float4 v = reinterpret_cast<const float4*>(in)[i];
    if (bias) {
        int col = (i * 4) & 127;
        v.x += bias[col]; v.y += bias[col + 1];
        v.z += bias[col + 2]; v.w += bias[col + 3];
    }
    if (do_relu) {
        v.x = fmaxf(v.x, 0.f); v.y = fmaxf(v.y, 0.f);
        v.z = fmaxf(v.z, 0.f); v.w = fmaxf(v.w, 0.f);
    }
    __nv_bfloat16 a0 = __float2bfloat16(v.x), a1 = __float2bfloat16(v.y);
    __nv_bfloat16 a2 = __float2bfloat16(v.z), a3 = __float2bfloat16(v.w);
    __nv_bfloat162 h0; h0.x = a0; h0.y = a1;
    __nv_bfloat162 h1; h1.x = a2; h1.y = a3;
    __nv_bfloat162 l0, l1;
    l0.x = __float2bfloat16(v.x - __bfloat162float(a0));
    l0.y = __float2bfloat16(v.y - __bfloat162float(a1));
    l1.x = __float2bfloat16(v.z - __bfloat162float(a2));
    l1.y = __float2bfloat16(v.w - __bfloat162float(a3));
    reinterpret_cast<__nv_bfloat162*>(hi)[i * 2]     = h0;
    reinterpret_cast<__nv_bfloat162*>(hi)[i * 2 + 1] = h1;
    reinterpret_cast<__nv_bfloat162*>(lo)[i * 2]     = l0;
    reinterpret_cast<__nv_bfloat162*>(lo)[i * 2 + 1] = l1;
}

__global__ void prep_t(const float* __restrict__ in, int K, int Nn,
                       __nv_bfloat16* __restrict__ hi, __nv_bfloat16* __restrict__ lo) {
    int idx = blockIdx.x * blockDim.x + threadIdx.x;
    if (idx >= K * Nn) return;
    int n = idx / K, k = idx - n * K;
    float v = in[(size_t)k * Nn + n];
    __nv_bfloat16 h = __float2bfloat16(v);
    hi[idx] = h;
    lo[idx] = __float2bfloat16(v - __bfloat162float(h));
}

__global__ void prep_rgcn(const float* __restrict__ root, const float* __restrict__ W,
                          __nv_bfloat16* __restrict__ hi, __nv_bfloat16* __restrict__ lo) {
    int idx = blockIdx.x * blockDim.x + threadIdx.x;
    if (idx >= 1152 * 128) return;
    int nrow = idx >> 7, k = idx & 127;
    float v;
    if (nrow < 128) v = root[(size_t)k * 128 + nrow];
    else {
        int r = (nrow >> 7) - 1, n = nrow & 127;
        v = W[((size_t)r * 128 + k) * 128 + n];
    }
    __nv_bfloat16 h = __float2bfloat16(v);
    hi[idx] = h;
    lo[idx] = __float2bfloat16(v - __bfloat162float(h));
}

// ---------------- GAT kernels --------------------------------------------------
__global__ void gat_alpha(const float* __restrict__ z, const float* __restrict__ att, int N) {
    int i = blockIdx.x * blockDim.x + threadIdx.x;
    if (i >= N * NHEADS) return;
    int n = i >> 3, h = i & 7;
    const float* zp = &z[(size_t)n * HD + h * DHH];
    float ss = 0.f, st = 0.f;
#pragma unroll
    for (int d = 0; d < DHH; d++) {
        float zv = zp[d];
        ss += zv * att[h * 2 * DHH + d];
        st += zv * att[h * 2 * DHH + DHH + d];
    }
    g_asrc[i] = ss; g_atgt[i] = st;
}

// one warp per SRC node (CSR-grouped): load z[s] once, loop its out-edges
__global__ void gat_accum2(const float* __restrict__ z, int N) {
    int s    = (blockIdx.x * blockDim.x + threadIdx.x) >> 5;
    int lane = threadIdx.x & 31;
    if (s >= N) return;
    int head = lane >> 2;
    float4 zv = *reinterpret_cast<const float4*>(&z[(size_t)s * HD + lane * 4]);
    float as = g_asrc[s * NHEADS + head];
    int e0 = (s == 0) ? 0 : g_ptr[(size_t)s * RRk - 1];
    int e1 = g_ptr[(size_t)s * RRk + RRk - 1];
    for (int e = e0; e < e1; e++) {
        int t = g_eTI[e].x;
        float a = as + g_atgt[t * NHEADS + head];
        a = (a > 0.f) ? a : 0.2f * a;
        float ex = __expf(a);
        red_add_v4(&g_num[(size_t)t * HD + lane * 4],
                   zv.x * ex, zv.y * ex, zv.z * ex, zv.w * ex);
        if ((lane & 3) == 0) atomicAdd(&g_denom[t * NHEADS + head], ex);
    }
}

__global__ void final_kernel(const float* __restrict__ bg, const float* __restrict__ Wf,
                             const float* __restrict__ bf, float* __restrict__ out, int N) {
    int w    = (blockIdx.x * blockDim.x + threadIdx.x) >> 5;
    int lane = threadIdx.x & 31;
    if (w >= N) return;
    int f0 = lane * 4;
    int head = lane >> 2;
    float4 nm = *reinterpret_cast<const float4*>(&g_num[(size_t)w * HD + f0]);
    float den = fmaxf(g_denom[w * NHEADS + head], 1e-16f);
    float gv[4] = { nm.x / den + bg[f0], nm.y / den + bg[f0 + 1],
                    nm.z / den + bg[f0 + 2], nm.w / den + bg[f0 + 3] };
    float s0 = 0.f, s1 = 0.f, s2 = 0.f;
#pragma unroll
    for (int i = 0; i < 4; i++) {
        const float* wr = &Wf[(f0 + i) * 3];
        s0 += gv[i] * wr[0]; s1 += gv[i] * wr[1]; s2 += gv[i] * wr[2];
    }
#pragma unroll
    for (int o = 16; o > 0; o >>= 1) {
        s0 += __shfl_xor_sync(0xffffffffu, s0, o);
        s1 += __shfl_xor_sync(0xffffffffu, s1, o);
        s2 += __shfl_xor_sync(0xffffffffu, s2, o);
    }
    if (lane == 0) {
        float l0 = s0 + bf[0], l1 = s1 + bf[1], l2 = s2 + bf[2];
        float m = fmaxf(l0, fmaxf(l1, l2));
        float lse = m + logf(expf(l0 - m) + expf(l1 - m) + expf(l2 - m));
        out[w * 3 + 0] = l0 - lse;
        out[w * 3 + 1] = l1 - lse;
        out[w * 3 + 2] = l2 - lse;
    }
}

// ---------------- host --------------------------------------------------------
extern "C" void kernel_launch(void* const* d_in, const int* in_sizes, int n_in,
                              void* d_out, int out_size)
{
    const float* x   = (const float*)d_in[0];
    const int*   ei  = (const int*)d_in[1];
    const int*   et  = (const int*)d_in[2];
    const float* Wp  = (const float*)d_in[3];
    const float* bp  = (const float*)d_in[4];
    const float* W1  = (const float*)d_in[5];
    const float* r1  = (const float*)d_in[6];
    const float* b1  = (const float*)d_in[7];
    const float* W2  = (const float*)d_in[8];
    const float* r2  = (const float*)d_in[9];
    const float* b2  = (const float*)d_in[10];
    const float* Wg  = (const float*)d_in[11];
    const float* att = (const float*)d_in[12];
    const float* bg  = (const float*)d_in[13];
    const float* Wf  = (const float*)d_in[14];
    const float* bf  = (const float*)d_in[15];
    float* out = (float*)d_out;

    const int N = in_sizes[0] / DINV;
    const int E = in_sizes[2];
    const int* src = ei;
    const int* tg  = ei + E;

    static cudaStream_t s1 = nullptr, s2 = nullptr;
    static cudaEvent_t ev0, evCsr, evWp, evW1, evH2, evNum, evW2, evSp1, evH1;
    if (!s1) {
        cudaStreamCreateWithFlags(&s1, cudaStreamNonBlocking);
        cudaStreamCreateWithFlags(&s2, cudaStreamNonBlocking);
        cudaEventCreateWithFlags(&ev0,   cudaEventDisableTiming);
        cudaEventCreateWithFlags(&evCsr, cudaEventDisableTiming);
        cudaEventCreateWithFlags(&evWp,  cudaEventDisableTiming);
        cudaEventCreateWithFlags(&evW1,  cudaEventDisableTiming);
        cudaEventCreateWithFlags(&evH2,  cudaEventDisableTiming);
        cudaEventCreateWithFlags(&evNum, cudaEventDisableTiming);
        cudaEventCreateWithFlags(&evW2,  cudaEventDisableTiming);
        cudaEventCreateWithFlags(&evSp1, cudaEventDisableTiming);
        cudaEventCreateWithFlags(&evH1,  cudaEventDisableTiming);
        cudaFuncSetAttribute(rgcn_all9, cudaFuncAttributeMaxDynamicSharedMemorySize, RGCN9_SMEM);
    }

    void *p_h1, *p_h2, *p_num, *p_deg, *p_denom, *p_cnt, *p_off;
    void *p_xhi, *p_xlo, *p_fhi, *p_flo;
    void *p_wph, *p_wpl, *p_w1h, *p_w1l, *p_w2h, *p_w2l, *p_wgh, *p_wgl;
    cudaGetSymbolAddress(&p_h1, g_h1);
    cudaGetSymbolAddress(&p_h2, g_h2);
    cudaGetSymbolAddress(&p_num, g_num);
    cudaGetSymbolAddress(&p_deg, g_deg);
    cudaGetSymbolAddress(&p_denom, g_denom);
    cudaGetSymbolAddress(&p_cnt, g_cnt);
    cudaGetSymbolAddress(&p_off, g_off);
    cudaGetSymbolAddress(&p_xhi, g_xhi);
    cudaGetSymbolAddress(&p_xlo, g_xlo);
    cudaGetSymbolAddress(&p_fhi, g_fhi);
    cudaGetSymbolAddress(&p_flo, g_flo);
    cudaGetSymbolAddress(&p_wph, g_wph);
    cudaGetSymbolAddress(&p_wpl, g_wpl);
    cudaGetSymbolAddress(&p_w1h, g_w1h);
    cudaGetSymbolAddress(&p_w1l, g_w1l);
    cudaGetSymbolAddress(&p_w2h, g_w2h);
    cudaGetSymbolAddress(&p_w2l, g_w2l);
    cudaGetSymbolAddress(&p_wgh, g_wgh);
    cudaGetSymbolAddress(&p_wgl, g_wgl);
    float* h1 = (float*)p_h1;
    float* h2 = (float*)p_h2;
    __nv_bfloat16* xhi = (__nv_bfloat16*)p_xhi;
    __nv_bfloat16* xlo = (__nv_bfloat16*)p_xlo;
    __nv_bfloat16* fhi = (__nv_bfloat16*)p_fhi;
    __nv_bfloat16* flo = (__nv_bfloat16*)p_flo;
    __nv_bfloat16* wph = (__nv_bfloat16*)p_wph, *wpl = (__nv_bfloat16*)p_wpl;
    __nv_bfloat16* w1h = (__nv_bfloat16*)p_w1h, *w1l = (__nv_bfloat16*)p_w1l;
    __nv_bfloat16* w2h = (__nv_bfloat16*)p_w2h, *w2l = (__nv_bfloat16*)p_w2l;
    __nv_bfloat16* wgh = (__nv_bfloat16*)p_wgh, *wgl = (__nv_bfloat16*)p_wgl;

    const int gx = (N + 127) / 128;
    const int nfeat4 = N * HD / 4;
    const int sblk = (NBINS + 1023) / 1024;
    const size_t hbytes = (size_t)N * HD * sizeof(float);

    cudaEventRecord(ev0, 0);

    // ---- s1: CSR build ----
    cudaStreamWaitEvent(s1, ev0, 0);
    cudaMemsetAsync(p_deg, 0, (size_t)N * RRk * sizeof(int), s1);
    cudaMemsetAsync(p_cnt, 0, (size_t)NBINS * sizeof(int), s1);
    cudaMemsetAsync(p_off, 0, (size_t)NBINS * sizeof(int), s1);
    count_kernel<<<(E + 255) / 256, 256, 0, s1>>>(src, tg, et, E);
    scan1<<<sblk, 1024, 0, s1>>>(NBINS);
    scan2<<<1, 512, 0, s1>>>(sblk);
    scan3<<<sblk, 1024, 0, s1>>>(NBINS);
    place_kernel<<<(E + 255) / 256, 256, 0, s1>>>(src, tg, et, E);
    cudaEventRecord(evCsr, s1);

    // ---- s2: weight preps + early memsets ----
    cudaStreamWaitEvent(s2, ev0, 0);
    prep_t<<<(DINV * HD + 255) / 256, 256, 0, s2>>>(Wp, DINV, HD, wph, wpl);
    cudaEventRecord(evWp, s2);
    prep_rgcn<<<(1152 * 128 + 255) / 256, 256, 0, s2>>>(r1, W1, w1h, w1l);
    cudaEventRecord(evW1, s2);
    cudaMemsetAsync(p_h2, 0, hbytes, s2);
    cudaEventRecord(evH2, s2);
    cudaMemsetAsync(p_num, 0, hbytes, s2);
    cudaMemsetAsync(p_denom, 0, (size_t)N * NHEADS * sizeof(float), s2);
    cudaEventRecord(evNum, s2);
    prep_rgcn<<<(1152 * 128 + 255) / 256, 256, 0, s2>>>(r2, W2, w2h, w2l);
    prep_t<<<(HD * HD + 255) / 256, 256, 0, s2>>>(Wg, HD, HD, wgh, wgl);
    cudaEventRecord(evW2, s2);

    // ---- main: projection ----
    split_kernel<<<(N * DINV / 4 + 255) / 256, 256>>>(x, xhi, xlo, N * DINV / 4, nullptr, 0);
    cudaStreamWaitEvent(0, evWp, 0);
    gemm_mma<<<gx, 256>>>(xhi, xlo, DINV, wph, wpl, bp, h1, N);
    split_kernel<<<(nfeat4 + 255) / 256, 256>>>(h1, fhi, flo, nfeat4, nullptr, 0);
    cudaEventRecord(evSp1, 0);

    // s2: h1 memset overlaps rgcn L1 (old h1 dead after split L1)
    cudaStreamWaitEvent(s2, evSp1, 0);
    cudaMemsetAsync(p_h1, 0, hbytes, s2);
    cudaEventRecord(evH1, s2);

    // ---- RGCN layer 1 (A-resident, root + 8 relations in one launch) ----
    cudaStreamWaitEvent(0, evW1, 0);
    cudaStreamWaitEvent(0, evCsr, 0);
    cudaStreamWaitEvent(0, evH2, 0);
    rgcn_all9<<<gx, 256, RGCN9_SMEM>>>(fhi, flo, w1h, w1l, h2, N);

    // ---- RGCN layer 2 (b1 + relu folded into split; b2 deferred) ----
    split_kernel<<<(nfeat4 + 255) / 256, 256>>>(h2, fhi, flo, nfeat4, b1, 1);
    cudaStreamWaitEvent(0, evW2, 0);
    cudaStreamWaitEvent(0, evH1, 0);
    rgcn_all9<<<gx, 256, RGCN9_SMEM>>>(fhi, flo, w2h, w2l, h1, N);

    // ---- GAT: z = relu(h1 + b2) @ Wg (stored in h2) ----
    split_kernel<<<(nfeat4 + 255) / 256, 256>>>(h1, fhi, flo, nfeat4, b2, 1);
    gemm_mma<<<gx, 256>>>(fhi, flo, HD, wgh, wgl, nullptr, h2, N);

    gat_alpha<<<(N * NHEADS + 255) / 256, 256>>>(h2, att, N);
    cudaStreamWaitEvent(0, evNum, 0);
    gat_accum2<<<(N + 7) / 8, 256>>>(h2, N);

    final_kernel<<<(N + 7) / 8, 256>>>(bg, Wf, bf, out, N);
}

// round 17
// speedup vs baseline: 1.2082x; 1.2082x over previous
#include <cuda_runtime.h>
#include <cuda_bf16.h>
#include <cstdint>

#define NN      50000
#define EE      800000
#define DINV    256
#define HD      128
#define RRk     8
#define NHEADS  8
#define DHH     16
#define P24     24            // smem pitch in bf16 (48B): conflict-free ldmatrix
#define NBINS   (NN * RRk)

// ---------------- scratch (static device arrays; no cudaMalloc) -------------
__device__ float g_h1[(size_t)NN * HD];
__device__ float g_h2[(size_t)NN * HD];
__device__ float g_num[(size_t)NN * HD];
__device__ int   g_deg[(size_t)NN * RRk];
__device__ float g_asrc[(size_t)NN * NHEADS];
__device__ float g_atgt[(size_t)NN * NHEADS];
__device__ float g_denom[(size_t)NN * NHEADS];

// CSR by (src, rel): bins of one src are contiguous
__device__ int  g_cnt[NBINS];
__device__ int  g_ptr[NBINS];
__device__ int  g_off[NBINS];
__device__ int  g_bsum[512];
__device__ int2 g_eTI[EE];        // (tgt, bitcast inv_deg)

__device__ __nv_bfloat16 g_xhi[(size_t)NN * DINV];
__device__ __nv_bfloat16 g_xlo[(size_t)NN * DINV];
__device__ __nv_bfloat16 g_fhi[(size_t)NN * HD];
__device__ __nv_bfloat16 g_flo[(size_t)NN * HD];
// dedicated weight buffers (enable overlap of all prep kernels)
__device__ __nv_bfloat16 g_wph[DINV * HD], g_wpl[DINV * HD];
__device__ __nv_bfloat16 g_w1h[(RRk + 1) * HD * HD], g_w1l[(RRk + 1) * HD * HD];
__device__ __nv_bfloat16 g_w2h[(RRk + 1) * HD * HD], g_w2l[(RRk + 1) * HD * HD];
__device__ __nv_bfloat16 g_wgh[HD * HD], g_wgl[HD * HD];

// ---------------- PTX helpers -------------------------------------------------
__device__ __forceinline__ uint32_t smem_to_u32(const void* p) {
    uint32_t a;
    asm("{ .reg .u64 t; cvta.to.shared.u64 t, %1; cvt.u32.u64 %0, t; }" : "=r"(a) : "l"(p));
    return a;
}
__device__ __forceinline__ void ldm_x4(unsigned* r, uint32_t a) {
    asm volatile("ldmatrix.sync.aligned.m8n8.x4.shared.b16 {%0,%1,%2,%3}, [%4];"
                 : "=r"(r[0]), "=r"(r[1]), "=r"(r[2]), "=r"(r[3]) : "r"(a));
}
__device__ __forceinline__ void mma_bf16(float* d, const unsigned* a, const unsigned* b) {
    asm volatile("mma.sync.aligned.m16n8k16.row.col.f32.bf16.bf16.f32 "
                 "{%0,%1,%2,%3}, {%4,%5,%6,%7}, {%8,%9}, {%0,%1,%2,%3};"
                 : "+f"(d[0]), "+f"(d[1]), "+f"(d[2]), "+f"(d[3])
                 : "r"(a[0]), "r"(a[1]), "r"(a[2]), "r"(a[3]), "r"(b[0]), "r"(b[1]));
}
__device__ __forceinline__ void cpa16(uint32_t dst, const void* src, int szbytes) {
    asm volatile("cp.async.ca.shared.global [%0], [%1], 16, %2;"
                 :: "r"(dst), "l"(src), "r"(szbytes) : "memory");
}
#define CP_COMMIT()  asm volatile("cp.async.commit_group;" ::: "memory")
#define CP_WAIT(n)   asm volatile("cp.async.wait_group %0;" :: "n"(n) : "memory")

__device__ __forceinline__ void red_add_v4(float* p, float a, float b, float c, float d) {
    asm volatile("red.global.add.v4.f32 [%0], {%1, %2, %3, %4};"
                 :: "l"(p), "f"(a), "f"(b), "f"(c), "f"(d) : "memory");
}

// ---------------- shared GEMM mainloop (2-stage cp.async, 128x128xK) ----------
#define STG (128 * P24)

#define GEMM_PROLOG_AND_MAINLOOP(BHI_PTR, BLO_PTR)                                     \
    __shared__ __align__(16) uint16_t sAh[2 * STG], sAl[2 * STG];                      \
    __shared__ __align__(16) uint16_t sBh[2 * STG], sBl[2 * STG];                      \
    const int tid    = threadIdx.x;                                                    \
    const int lane   = tid & 31, wid = tid >> 5;                                       \
    const int warp_m = wid & 1;                                                        \
    const int warp_n = wid >> 1;                                                       \
    const int m0     = blockIdx.x * 128;                                               \
    const int lrow  = tid >> 1, lhalf = tid & 1;                                       \
    const int jj    = lane >> 3, rin = lane & 7;                                       \
    const int a_r   = (jj & 1) * 8 + rin;                                              \
    const int a_c   = (jj >> 1) * 8;                                                   \
    const uint32_t bAh = smem_to_u32(sAh), bAl = smem_to_u32(sAl);                     \
    const uint32_t bBh = smem_to_u32(sBh), bBl = smem_to_u32(sBl);                     \
    const uint32_t soff = (lrow * P24 + lhalf * 8) * 2;                                \
    const int gr = m0 + lrow;                                                          \
    const int aSz = (gr < M) ? 16 : 0;                                                 \
    const size_t aRow = (size_t)((gr < M) ? gr : 0) * Ktot + lhalf * 8;                \
    const size_t bRow = (size_t)lrow * Ktot + lhalf * 8;                               \
    float acc[4][4][4];                                                                \
    _Pragma("unroll") for (int i = 0; i < 4; i++)                                      \
    _Pragma("unroll") for (int j = 0; j < 4; j++)                                      \
    _Pragma("unroll") for (int q = 0; q < 4; q++) acc[i][j][q] = 0.f;                  \
    const int nIter = Ktot >> 4;                                                       \
    cpa16(bAh + soff, Ahi + aRow, aSz);                                                \
    cpa16(bAl + soff, Alo + aRow, aSz);                                                \
    cpa16(bBh + soff, (BHI_PTR) + bRow, 16);                                           \
    cpa16(bBl + soff, (BLO_PTR) + bRow, 16);                                           \
    CP_COMMIT();                                                                       \
    for (int it = 0; it < nIter; it++) {                                               \
        if (it + 1 < nIter) {                                                          \
            uint32_t st = ((it + 1) & 1) * STG * 2;                                    \
            int k0 = (it + 1) << 4;                                                    \
            cpa16(bAh + st + soff, Ahi + aRow + k0, aSz);                              \
            cpa16(bAl + st + soff, Alo + aRow + k0, aSz);                              \
            cpa16(bBh + st + soff, (BHI_PTR) + bRow + k0, 16);                         \
            cpa16(bBl + st + soff, (BLO_PTR) + bRow + k0, 16);                         \
            CP_COMMIT(); CP_WAIT(1);                                                   \
        } else { CP_WAIT(0); }                                                         \
        __syncthreads();                                                               \
        const uint32_t st = (it & 1) * STG * 2;                                        \
        unsigned ah[4][4], al[4][4], bh[4][2], bl[4][2];                               \
        _Pragma("unroll") for (int i = 0; i < 4; i++) {                                \
            int row = warp_m * 64 + i * 16 + a_r;                                      \
            ldm_x4(ah[i], bAh + st + (row * P24 + a_c) * 2);                           \
            ldm_x4(al[i], bAl + st + (row * P24 + a_c) * 2);                           \
        }                                                                              \
        _Pragma("unroll") for (int p = 0; p < 2; p++) {                                \
            int row = warp_n * 32 + p * 16 + a_r;                                      \
            unsigned t[4];                                                             \
            ldm_x4(t, bBh + st + (row * P24 + a_c) * 2);                               \
            bh[p * 2][0] = t[0]; bh[p * 2][1] = t[2];                                  \
            bh[p * 2 + 1][0] = t[1]; bh[p * 2 + 1][1] = t[3];                          \
            ldm_x4(t, bBl + st + (row * P24 + a_c) * 2);                               \
            bl[p * 2][0] = t[0]; bl[p * 2][1] = t[2];                                  \
            bl[p * 2 + 1][0] = t[1]; bl[p * 2 + 1][1] = t[3];                          \
        }                                                                              \
        _Pragma("unroll") for (int i = 0; i < 4; i++)                                  \
        _Pragma("unroll") for (int j = 0; j < 4; j++) {                                \
            mma_bf16(acc[i][j], ah[i], bh[j]);                                         \
            mma_bf16(acc[i][j], ah[i], bl[j]);                                         \
            mma_bf16(acc[i][j], al[i], bh[j]);                                         \
        }                                                                              \
        __syncthreads();                                                               \
    }

// Plain GEMM: C = A @ B^T (+bias). Used for projection and GAT z.
__global__ __launch_bounds__(256)
void gemm_mma(const __nv_bfloat16* __restrict__ Ahi, const __nv_bfloat16* __restrict__ Alo,
              int Ktot,
              const __nv_bfloat16* __restrict__ Bhi, const __nv_bfloat16* __restrict__ Blo,
              const float* __restrict__ bias,
              float* __restrict__ C, int M)
{
    GEMM_PROLOG_AND_MAINLOOP(Bhi, Blo)

    const int mrow = m0 + warp_m * 64 + (lane >> 2);
    const int ncol = warp_n * 32 + (lane & 3) * 2;
#pragma unroll
    for (int i = 0; i < 4; i++) {
#pragma unroll
        for (int j = 0; j < 4; j++) {
            int col = ncol + j * 8;
            float bv0 = bias ? bias[col] : 0.f;
            float bv1 = bias ? bias[col + 1] : 0.f;
            int mm = mrow + i * 16;
            if (mm < M)
                *reinterpret_cast<float2*>(C + (size_t)mm * HD + col) =
                    make_float2(acc[i][j][0] + bv0, acc[i][j][1] + bv1);
            if (mm + 8 < M)
                *reinterpret_cast<float2*>(C + (size_t)(mm + 8) * HD + col) =
                    make_float2(acc[i][j][2] + bv0, acc[i][j][3] + bv1);
        }
    }
}

// Full RGCN layer in one launch. Slab by==0: root term (H pre-zeroed, bias
// folded into downstream split). Slabs 1..8: relation r=by-1, scatter
// H[tgt,:] += (A@W_r^T)[m,:]*inv_deg via CSR bins.
// Epilogue uses pairwise shfl regrouping so each edge issues 2 red.add.v4
// (16B sectors) instead of 4 red.add.v2 — halves LTS atomic ops.
__global__ __launch_bounds__(256)
void rgcn_all(const __nv_bfloat16* __restrict__ Ahi, const __nv_bfloat16* __restrict__ Alo,
              const __nv_bfloat16* __restrict__ BhiAll, const __nv_bfloat16* __restrict__ BloAll,
              float* __restrict__ H, int M)
{
    const int by = blockIdx.y;     // 0 = root, 1..8 = relation by-1
    const int Ktot = HD;
    const __nv_bfloat16* Bhi = BhiAll + (size_t)by * 128 * HD;
    const __nv_bfloat16* Blo = BloAll + (size_t)by * 128 * HD;

    GEMM_PROLOG_AND_MAINLOOP(Bhi, Blo)

    const int mBase = m0 + warp_m * 64 + (lane >> 2);
    const bool evenl = (lane & 1) == 0;
    // column of this thread's first float4 after pairwise regrouping
    const int cw = warp_n * 32 + (evenl ? (lane & 3) * 2 : ((lane & 3) - 1) * 2 + 16);

#pragma unroll
    for (int i = 0; i < 4; i++) {
#pragma unroll
        for (int p = 0; p < 2; p++) {
            const int p2 = p * 2;
            // full-warp exchange (before any divergence; pair lane^1 shares m)
            float s0 = evenl ? acc[i][2][p2]     : acc[i][0][p2];
            float s1 = evenl ? acc[i][2][p2 + 1] : acc[i][0][p2 + 1];
            float s2 = evenl ? acc[i][3][p2]     : acc[i][1][p2];
            float s3 = evenl ? acc[i][3][p2 + 1] : acc[i][1][p2 + 1];
            float r0 = __shfl_xor_sync(0xffffffffu, s0, 1);
            float r1 = __shfl_xor_sync(0xffffffffu, s1, 1);
            float r2 = __shfl_xor_sync(0xffffffffu, s2, 1);
            float r3 = __shfl_xor_sync(0xffffffffu, s3, 1);
            float v0[4], v1[4];
            if (evenl) {
                v0[0] = acc[i][0][p2]; v0[1] = acc[i][0][p2 + 1]; v0[2] = r0; v0[3] = r1;
                v1[0] = acc[i][1][p2]; v1[1] = acc[i][1][p2 + 1]; v1[2] = r2; v1[3] = r3;
            } else {
                v0[0] = r0; v0[1] = r1; v0[2] = acc[i][2][p2]; v0[3] = acc[i][2][p2 + 1];
                v1[0] = r2; v1[1] = r3; v1[2] = acc[i][3][p2]; v1[3] = acc[i][3][p2 + 1];
            }

            const int m = mBase + i * 16 + p * 8;
            if (m >= M) continue;

            if (by == 0) {
                float* base = H + (size_t)m * HD + cw;
                red_add_v4(base,     v0[0], v0[1], v0[2], v0[3]);
                red_add_v4(base + 8, v1[0], v1[1], v1[2], v1[3]);
            } else {
                const int bin = (m << 3) + (by - 1);
                int e0 = bin ? g_ptr[bin - 1] : 0;
                int e1 = g_ptr[bin];
                for (int e = e0; e < e1; e++) {
                    int2 ti = g_eTI[e];
                    float inv = __int_as_float(ti.y);
                    float* base = H + (size_t)ti.x * HD + cw;
                    red_add_v4(base,     v0[0] * inv, v0[1] * inv, v0[2] * inv, v0[3] * inv);
                    red_add_v4(base + 8, v1[0] * inv, v1[1] * inv, v1[2] * inv, v1[3] * inv);
                }
            }
        }
    }
}

// ---------------- CSR build ----------------------------------------------------
__global__ void count_kernel(const int* __restrict__ src, const int* __restrict__ tgt,
                             const int* __restrict__ et, int E) {
    int i = blockIdx.x * blockDim.x + threadIdx.x;
    if (i >= E) return;
    int r = et[i];
    atomicAdd(&g_deg[(size_t)tgt[i] * RRk + r], 1);
    atomicAdd(&g_cnt[(size_t)src[i] * RRk + r], 1);
}

__global__ void scan1(int n) {
    __shared__ int sh[1024];
    int i = blockIdx.x * 1024 + threadIdx.x;
    int v = (i < n) ? g_cnt[i] : 0;
    sh[threadIdx.x] = v;
    __syncthreads();
    for (int o = 1; o < 1024; o <<= 1) {
        int t = (threadIdx.x >= o) ? sh[threadIdx.x - o] : 0;
        __syncthreads();
        sh[threadIdx.x] += t;
        __syncthreads();
    }
    if (i < n) g_ptr[i] = sh[threadIdx.x];
    if (threadIdx.x == 1023) g_bsum[blockIdx.x] = sh[1023];
}
__global__ void scan2(int nb) {
    __shared__ int sh[512];
    int v = (threadIdx.x < nb) ? g_bsum[threadIdx.x] : 0;
    sh[threadIdx.x] = v;
    __syncthreads();
    for (int o = 1; o < 512; o <<= 1) {
        int t = (threadIdx.x >= o) ? sh[threadIdx.x - o] : 0;
        __syncthreads();
        sh[threadIdx.x] += t;
        __syncthreads();
    }
    if (threadIdx.x < nb) g_bsum[threadIdx.x] = sh[threadIdx.x];
}
__global__ void scan3(int n) {
    int i = blockIdx.x * 1024 + threadIdx.x;
    if (i >= n || blockIdx.x == 0) return;
    g_ptr[i] += g_bsum[blockIdx.x - 1];
}
__global__ void place_kernel(const int* __restrict__ src, const int* __restrict__ tgt,
                             const int* __restrict__ et, int E) {
    int i = blockIdx.x * blockDim.x + threadIdx.x;
    if (i >= E) return;
    int r = et[i], s = src[i], t = tgt[i];
    int bin = s * RRk + r;
    int base = bin ? g_ptr[bin - 1] : 0;
    int pos = base + atomicAdd(&g_off[bin], 1);
    int d = g_deg[(size_t)t * RRk + r];
    float inv = 1.f / (float)(d > 1 ? d : 1);
    g_eTI[pos] = make_int2(t, __float_as_int(inv));
}

// ---------------- split / weight-prep kernels --------------------------------
__global__ void split_kernel(const float* __restrict__ in, __nv_bfloat16* __restrict__ hi,
                             __nv_bfloat16* __restrict__ lo, int n4,
                             const float* __restrict__ bias, int do_relu) {
    int i = blockIdx.x * blockDim.x + threadIdx.x;
    if (i >= n4) return;
    float4 v = reinterpret_cast<const float4*>(in)[i];
    if (bias) {
        int col = (i * 4) & 127;
        v.x += bias[col]; v.y += bias[col + 1];
        v.z += bias[col + 2]; v.w += bias[col + 3];
    }
    if (do_relu) {
        v.x = fmaxf(v.x, 0.f); v.y = fmaxf(v.y, 0.f);
        v.z = fmaxf(v.z, 0.f); v.w = fmaxf(v.w, 0.f);
    }
    __nv_bfloat16 a0 = __float2bfloat16(v.x), a1 = __float2bfloat16(v.y);
    __nv_bfloat16 a2 = __float2bfloat16(v.z), a3 = __float2bfloat16(v.w);
    __nv_bfloat162 h0; h0.x = a0; h0.y = a1;
    __nv_bfloat162 h1; h1.x = a2; h1.y = a3;
    __nv_bfloat162 l0, l1;
    l0.x = __float2bfloat16(v.x - __bfloat162float(a0));
    l0.y = __float2bfloat16(v.y - __bfloat162float(a1));
    l1.x = __float2bfloat16(v.z - __bfloat162float(a2));
    l1.y = __float2bfloat16(v.w - __bfloat162float(a3));
    reinterpret_cast<__nv_bfloat162*>(hi)[i * 2]     = h0;
    reinterpret_cast<__nv_bfloat162*>(hi)[i * 2 + 1] = h1;
    reinterpret_cast<__nv_bfloat162*>(lo)[i * 2]     = l0;
    reinterpret_cast<__nv_bfloat162*>(lo)[i * 2 + 1] = l1;
}

__global__ void prep_t(const float* __restrict__ in, int K, int Nn,
                       __nv_bfloat16* __restrict__ hi, __nv_bfloat16* __restrict__ lo) {
    int idx = blockIdx.x * blockDim.x + threadIdx.x;
    if (idx >= K * Nn) return;
    int n = idx / K, k = idx - n * K;
    float v = in[(size_t)k * Nn + n];
    __nv_bfloat16 h = __float2bfloat16(v);
    hi[idx] = h;
    lo[idx] = __float2bfloat16(v - __bfloat162float(h));
}

__global__ void prep_rgcn(const float* __restrict__ root, const float* __restrict__ W,
                          __nv_bfloat16* __restrict__ hi, __nv_bfloat16* __restrict__ lo) {
    int idx = blockIdx.x * blockDim.x + threadIdx.x;
    if (idx >= 1152 * 128) return;
    int nrow = idx >> 7, k = idx & 127;
    float v;
    if (nrow < 128) v = root[(size_t)k * 128 + nrow];
    else {
        int r = (nrow >> 7) - 1, n = nrow & 127;
        v = W[((size_t)r * 128 + k) * 128 + n];
    }
    __nv_bfloat16 h = __float2bfloat16(v);
    hi[idx] = h;
    lo[idx] = __float2bfloat16(v - __bfloat162float(h));
}

// ---------------- GAT kernels --------------------------------------------------
__global__ void gat_alpha(const float* __restrict__ z, const float* __restrict__ att, int N) {
    int i = blockIdx.x * blockDim.x + threadIdx.x;
    if (i >= N * NHEADS) return;
    int n = i >> 3, h = i & 7;
    const float* zp = &z[(size_t)n * HD + h * DHH];
    float ss = 0.f, st = 0.f;
#pragma unroll
    for (int d = 0; d < DHH; d++) {
        float zv = zp[d];
        ss += zv * att[h * 2 * DHH + d];
        st += zv * att[h * 2 * DHH + DHH + d];
    }
    g_asrc[i] = ss; g_atgt[i] = st;
}

// one warp per SRC node (CSR-grouped): load z[s] once, loop its out-edges
__global__ void gat_accum2(const float* __restrict__ z, int N) {
    int s    = (blockIdx.x * blockDim.x + threadIdx.x) >> 5;
    int lane = threadIdx.x & 31;
    if (s >= N) return;
    int head = lane >> 2;
    float4 zv = *reinterpret_cast<const float4*>(&z[(size_t)s * HD + lane * 4]);
    float as = g_asrc[s * NHEADS + head];
    int e0 = (s == 0) ? 0 : g_ptr[(size_t)s * RRk - 1];
    int e1 = g_ptr[(size_t)s * RRk + RRk - 1];
    for (int e = e0; e < e1; e++) {
        int t = g_eTI[e].x;
        float a = as + g_atgt[t * NHEADS + head];
        a = (a > 0.f) ? a : 0.2f * a;
        float ex = __expf(a);
        red_add_v4(&g_num[(size_t)t * HD + lane * 4],
                   zv.x * ex, zv.y * ex, zv.z * ex, zv.w * ex);
        if ((lane & 3) == 0) atomicAdd(&g_denom[t * NHEADS + head], ex);
    }
}

__global__ void final_kernel(const float* __restrict__ bg, const float* __restrict__ Wf,
                             const float* __restrict__ bf, float* __restrict__ out, int N) {
    int w    = (blockIdx.x * blockDim.x + threadIdx.x) >> 5;
    int lane = threadIdx.x & 31;
    if (w >= N) return;
    int f0 = lane * 4;
    int head = lane >> 2;
    float4 nm = *reinterpret_cast<const float4*>(&g_num[(size_t)w * HD + f0]);
    float den = fmaxf(g_denom[w * NHEADS + head], 1e-16f);
    float gv[4] = { nm.x / den + bg[f0], nm.y / den + bg[f0 + 1],
                    nm.z / den + bg[f0 + 2], nm.w / den + bg[f0 + 3] };
    float s0 = 0.f, s1 = 0.f, s2 = 0.f;
#pragma unroll
    for (int i = 0; i < 4; i++) {
        const float* wr = &Wf[(f0 + i) * 3];
        s0 += gv[i] * wr[0]; s1 += gv[i] * wr[1]; s2 += gv[i] * wr[2];
    }
#pragma unroll
    for (int o = 16; o > 0; o >>= 1) {
        s0 += __shfl_xor_sync(0xffffffffu, s0, o);
        s1 += __shfl_xor_sync(0xffffffffu, s1, o);
        s2 += __shfl_xor_sync(0xffffffffu, s2, o);
    }
    if (lane == 0) {
        float l0 = s0 + bf[0], l1 = s1 + bf[1], l2 = s2 + bf[2];
        float m = fmaxf(l0, fmaxf(l1, l2));
        float lse = m + logf(expf(l0 - m) + expf(l1 - m) + expf(l2 - m));
        out[w * 3 + 0] = l0 - lse;
        out[w * 3 + 1] = l1 - lse;
        out[w * 3 + 2] = l2 - lse;
    }
}

// ---------------- host --------------------------------------------------------
extern "C" void kernel_launch(void* const* d_in, const int* in_sizes, int n_in,
                              void* d_out, int out_size)
{
    const float* x   = (const float*)d_in[0];
    const int*   ei  = (const int*)d_in[1];
    const int*   et  = (const int*)d_in[2];
    const float* Wp  = (const float*)d_in[3];
    const float* bp  = (const float*)d_in[4];
    const float* W1  = (const float*)d_in[5];
    const float* r1  = (const float*)d_in[6];
    const float* b1  = (const float*)d_in[7];
    const float* W2  = (const float*)d_in[8];
    const float* r2  = (const float*)d_in[9];
    const float* b2  = (const float*)d_in[10];
    const float* Wg  = (const float*)d_in[11];
    const float* att = (const float*)d_in[12];
    const float* bg  = (const float*)d_in[13];
    const float* Wf  = (const float*)d_in[14];
    const float* bf  = (const float*)d_in[15];
    float* out = (float*)d_out;

    const int N = in_sizes[0] / DINV;
    const int E = in_sizes[2];
    const int* src = ei;
    const int* tg  = ei + E;

    static cudaStream_t s1 = nullptr, s2 = nullptr;
    static cudaEvent_t ev0, evCsr, evWp, evW1, evH2, evNum, evW2, evSp1, evH1;
    if (!s1) {
        cudaStreamCreateWithFlags(&s1, cudaStreamNonBlocking);
        cudaStreamCreateWithFlags(&s2, cudaStreamNonBlocking);
        cudaEventCreateWithFlags(&ev0,   cudaEventDisableTiming);
        cudaEventCreateWithFlags(&evCsr, cudaEventDisableTiming);
        cudaEventCreateWithFlags(&evWp,  cudaEventDisableTiming);
        cudaEventCreateWithFlags(&evW1,  cudaEventDisableTiming);
        cudaEventCreateWithFlags(&evH2,  cudaEventDisableTiming);
        cudaEventCreateWithFlags(&evNum, cudaEventDisableTiming);
        cudaEventCreateWithFlags(&evW2,  cudaEventDisableTiming);
        cudaEventCreateWithFlags(&evSp1, cudaEventDisableTiming);
        cudaEventCreateWithFlags(&evH1,  cudaEventDisableTiming);
    }

    void *p_h1, *p_h2, *p_num, *p_deg, *p_denom, *p_cnt, *p_off;
    void *p_xhi, *p_xlo, *p_fhi, *p_flo;
    void *p_wph, *p_wpl, *p_w1h, *p_w1l, *p_w2h, *p_w2l, *p_wgh, *p_wgl;
    cudaGetSymbolAddress(&p_h1, g_h1);
    cudaGetSymbolAddress(&p_h2, g_h2);
    cudaGetSymbolAddress(&p_num, g_num);
    cudaGetSymbolAddress(&p_deg, g_deg);
    cudaGetSymbolAddress(&p_denom, g_denom);
    cudaGetSymbolAddress(&p_cnt, g_cnt);
    cudaGetSymbolAddress(&p_off, g_off);
    cudaGetSymbolAddress(&p_xhi, g_xhi);
    cudaGetSymbolAddress(&p_xlo, g_xlo);
    cudaGetSymbolAddress(&p_fhi, g_fhi);
    cudaGetSymbolAddress(&p_flo, g_flo);
    cudaGetSymbolAddress(&p_wph, g_wph);
    cudaGetSymbolAddress(&p_wpl, g_wpl);
    cudaGetSymbolAddress(&p_w1h, g_w1h);
    cudaGetSymbolAddress(&p_w1l, g_w1l);
    cudaGetSymbolAddress(&p_w2h, g_w2h);
    cudaGetSymbolAddress(&p_w2l, g_w2l);
    cudaGetSymbolAddress(&p_wgh, g_wgh);
    cudaGetSymbolAddress(&p_wgl, g_wgl);
    float* h1 = (float*)p_h1;
    float* h2 = (float*)p_h2;
    __nv_bfloat16* xhi = (__nv_bfloat16*)p_xhi;
    __nv_bfloat16* xlo = (__nv_bfloat16*)p_xlo;
    __nv_bfloat16* fhi = (__nv_bfloat16*)p_fhi;
    __nv_bfloat16* flo = (__nv_bfloat16*)p_flo;
    __nv_bfloat16* wph = (__nv_bfloat16*)p_wph, *wpl = (__nv_bfloat16*)p_wpl;
    __nv_bfloat16* w1h = (__nv_bfloat16*)p_w1h, *w1l = (__nv_bfloat16*)p_w1l;
    __nv_bfloat16* w2h = (__nv_bfloat16*)p_w2h, *w2l = (__nv_bfloat16*)p_w2l;
    __nv_bfloat16* wgh = (__nv_bfloat16*)p_wgh, *wgl = (__nv_bfloat16*)p_wgl;

    const int gx = (N + 127) / 128;
    const int nfeat4 = N * HD / 4;
    const int sblk = (NBINS + 1023) / 1024;
    const size_t hbytes = (size_t)N * HD * sizeof(float);

    cudaEventRecord(ev0, 0);

    // ---- s1: CSR build ----
    cudaStreamWaitEvent(s1, ev0, 0);
    cudaMemsetAsync(p_deg, 0, (size_t)N * RRk * sizeof(int), s1);
    cudaMemsetAsync(p_cnt, 0, (size_t)NBINS * sizeof(int), s1);
    cudaMemsetAsync(p_off, 0, (size_t)NBINS * sizeof(int), s1);
    count_kernel<<<(E + 255) / 256, 256, 0, s1>>>(src, tg, et, E);
    scan1<<<sblk, 1024, 0, s1>>>(NBINS);
    scan2<<<1, 512, 0, s1>>>(sblk);
    scan3<<<sblk, 1024, 0, s1>>>(NBINS);
    place_kernel<<<(E + 255) / 256, 256, 0, s1>>>(src, tg, et, E);
    cudaEventRecord(evCsr, s1);

    // ---- s2: weight preps + early memsets ----
    cudaStreamWaitEvent(s2, ev0, 0);
    prep_t<<<(DINV * HD + 255) / 256, 256, 0, s2>>>(Wp, DINV, HD, wph, wpl);
    cudaEventRecord(evWp, s2);
    prep_rgcn<<<(1152 * 128 + 255) / 256, 256, 0, s2>>>(r1, W1, w1h, w1l);
    cudaEventRecord(evW1, s2);
    cudaMemsetAsync(p_h2, 0, hbytes, s2);
    cudaEventRecord(evH2, s2);
    cudaMemsetAsync(p_num, 0, hbytes, s2);
    cudaMemsetAsync(p_denom, 0, (size_t)N * NHEADS * sizeof(float), s2);
    cudaEventRecord(evNum, s2);
    prep_rgcn<<<(1152 * 128 + 255) / 256, 256, 0, s2>>>(r2, W2, w2h, w2l);
    prep_t<<<(HD * HD + 255) / 256, 256, 0, s2>>>(Wg, HD, HD, wgh, wgl);
    cudaEventRecord(evW2, s2);

    // ---- main: projection ----
    split_kernel<<<(N * DINV / 4 + 255) / 256, 256>>>(x, xhi, xlo, N * DINV / 4, nullptr, 0);
    cudaStreamWaitEvent(0, evWp, 0);
    gemm_mma<<<gx, 256>>>(xhi, xlo, DINV, wph, wpl, bp, h1, N);
    split_kernel<<<(nfeat4 + 255) / 256, 256>>>(h1, fhi, flo, nfeat4, nullptr, 0);
    cudaEventRecord(evSp1, 0);

    // s2: h1 memset overlaps rgcn L1 (old h1 dead after split L1)
    cudaStreamWaitEvent(s2, evSp1, 0);
    cudaMemsetAsync(p_h1, 0, hbytes, s2);
    cudaEventRecord(evH1, s2);

    // ---- RGCN layer 1 (root + 8 relations, one launch; bias b1 deferred) ----
    cudaStreamWaitEvent(0, evW1, 0);
    cudaStreamWaitEvent(0, evCsr, 0);
    cudaStreamWaitEvent(0, evH2, 0);
    rgcn_all<<<dim3(gx, RRk + 1), 256>>>(fhi, flo, w1h, w1l, h2, N);

    // ---- RGCN layer 2 (b1 + relu folded into split; b2 deferred) ----
    split_kernel<<<(nfeat4 + 255) / 256, 256>>>(h2, fhi, flo, nfeat4, b1, 1);
    cudaStreamWaitEvent(0, evW2, 0);
    cudaStreamWaitEvent(0, evH1, 0);
    rgcn_all<<<dim3(gx, RRk + 1), 256>>>(fhi, flo, w2h, w2l, h1, N);

    // ---- GAT: z = relu(h1 + b2) @ Wg (stored in h2) ----
    split_kernel<<<(nfeat4 + 255) / 256, 256>>>(h1, fhi, flo, nfeat4, b2, 1);
    gemm_mma<<<gx, 256>>>(fhi, flo, HD, wgh, wgl, nullptr, h2, N);

    gat_alpha<<<(N * NHEADS + 255) / 256, 256>>>(h2, att, N);
    cudaStreamWaitEvent(0, evNum, 0);
    gat_accum2<<<(N + 7) / 8, 256>>>(h2, N);

    final_kernel<<<(N + 7) / 8, 256>>>(bg, Wf, bf, out, N);
}